// round 17
// baseline (speedup 1.0000x reference)
#include <cuda_runtime.h>
#include <cstdint>

// ============================================================================
//   out[b, f*32+e] = sum_h relu(x[b,f]*w1[f,h]+b1[f,h]) * w2[f,h,e] + b2[f,e]
//
// Piecewise-linear reformulation: for fixed f, out = x*Sw(rank)[e]+Sb(rank)[e],
// rank = #breakpoints below x. Fused prep (vectorized transpose + per-feature
// tables via parallel deltas), then persistent single-wave main kernel
// (512 threads, 4 CTAs/SM = 100% occ): binary search + pair-row float4 table
// reads + STG.64 stores.
// ============================================================================
#define B_TOT 16384
#define F_TOT 128
#define H_DIM 128
#define E_DIM 32

static constexpr int ROWS_PER_ITEM = 512;                         // one CTA sweep
static constexpr int N_ITEMS  = F_TOT * (B_TOT / ROWS_PER_ITEM);  // 4096
static constexpr int TSTR     = 34;   // tab row stride in float2 (16B-aligned)

// ---- device scratch (static allocation allowed) ----
__device__ float2 g_table[F_TOT][H_DIM + 1][E_DIM];   // {Sw, Sb} per rank
__device__ float  g_thresh[F_TOT][H_DIM];             // sorted breakpoints
__device__ float  g_xT[F_TOT][B_TOT];                 // x transposed

// ============================================================================
// Kernel 1: fused prep.
//   CTAs [0, 512): transpose x [B,F] -> xT [F,B], 32 rows x 128 f per CTA
//   CTAs [512, 640): per-feature breakpoint sort + prefix tables
// ============================================================================
__global__ void __launch_bounds__(256)
prep_kernel(const float* __restrict__ x,
            const float* __restrict__ w1, const float* __restrict__ b1,
            const float* __restrict__ w2, const float* __restrict__ b2)
{
    const int c   = blockIdx.x;
    const int tid = threadIdx.x;

    if (c < 512) {
        // ---------------- transpose part (vectorized) ----------------
        __shared__ float tile[32][129];
        const int b0 = c * 32;
        #pragma unroll
        for (int i = 0; i < 4; i++) {
            const int flat = (i * 256 + tid) * 4;      // float index
            const int r = flat >> 7, fq = flat & 127;
            const float4 v = *reinterpret_cast<const float4*>(
                &x[(size_t)(b0 + r) * F_TOT + fq]);
            tile[r][fq]     = v.x;
            tile[r][fq + 1] = v.y;
            tile[r][fq + 2] = v.z;
            tile[r][fq + 3] = v.w;
        }
        __syncthreads();
        const int lane = tid & 31, warp = tid >> 5;
        #pragma unroll
        for (int k = 0; k < 16; k++) {
            const int f = k * 8 + warp;
            g_xT[f][b0 + lane] = tile[lane][f];
        }
        return;
    }

    // ---------------- precompute part (one CTA per feature) ----------------
    const int f = c - 512;
    const float* w2f = w2 + (size_t)f * (H_DIM * E_DIM);

    __shared__ float2 dlt[H_DIM][E_DIM];      // per-rank {dW, dB} deltas, 32 KB
    __shared__ float2 bpart[8][E_DIM];        // base partial sums
    __shared__ float  tS[H_DIM];
    __shared__ int    hS[H_DIM];
    __shared__ float  w1s[H_DIM], b1s[H_DIM];

    if (tid < H_DIM) {
        const float wv = w1[f * H_DIM + tid];
        const float bv = b1[f * H_DIM + tid];
        w1s[tid] = wv;
        b1s[tid] = bv;
        tS[tid] = (wv != 0.0f) ? (-bv / wv) : __int_as_float(0x7f800000);
        hS[tid] = tid;
    }
    __syncthreads();

    // bitonic sort (ascending) on (tS, hS), 128 elems; barriers CTA-wide
    for (int k = 2; k <= H_DIM; k <<= 1) {
        for (int j = k >> 1; j > 0; j >>= 1) {
            if (tid < H_DIM) {
                const int ix = tid ^ j;
                if (ix > tid) {
                    const bool up = ((tid & k) == 0);
                    const float a = tS[tid], cc = tS[ix];
                    if ((a > cc) == up) {
                        tS[tid] = cc; tS[ix] = a;
                        const int hh = hS[tid]; hS[tid] = hS[ix]; hS[ix] = hh;
                    }
                }
            }
            __syncthreads();
        }
    }

    if (tid < H_DIM) g_thresh[f][tid] = tS[tid];

    // parallel per-rank deltas: crossing rank r upward toggles unit hS[r]
    for (int i = tid; i < H_DIM * E_DIM; i += 256) {
        const int r = i >> 5, e = i & 31;
        const int h = hS[r];
        const float w = w1s[h];
        const float sign = (w > 0.0f) ? 1.0f : ((w < 0.0f) ? -1.0f : 0.0f);
        const float w2v = w2f[h * E_DIM + e];
        dlt[r][e] = make_float2(sign * w * w2v, sign * b1s[h] * w2v);
    }

    // parallel base state at x = -inf (8 partials x 32 e)
    {
        const int e = tid & 31, part = tid >> 5;
        float sW = 0.0f, sB = 0.0f;
        for (int h = part * 16; h < part * 16 + 16; h++) {
            const float w = w1s[h], b = b1s[h];
            const float w2v = w2f[h * E_DIM + e];
            if (w < 0.0f)                 { sW += w * w2v; sB += b * w2v; }
            else if (w == 0.0f && b > 0.0f) sB += b * w2v;
        }
        bpart[part][e] = make_float2(sW, sB);
    }
    __syncthreads();

    // sequential accumulation over ranks (LDS.64 + FADD per step, 32 threads)
    if (tid < E_DIM) {
        const int e = tid;
        float sW = 0.0f, sB = b2[f * E_DIM + e];
        #pragma unroll
        for (int p = 0; p < 8; p++) { sW += bpart[p][e].x; sB += bpart[p][e].y; }
        g_table[f][0][e] = make_float2(sW, sB);
        for (int r = 0; r < H_DIM; r++) {
            const float2 d = dlt[r][e];
            sW += d.x; sB += d.y;
            g_table[f][r + 1][e] = make_float2(sW, sB);
        }
    }
}

// ============================================================================
// Kernel 2: main — persistent single-wave 512-thread CTAs (4/SM, 64 warps)
//   over f-major 512-row items. One sweep per item: each warp searches its
//   32 rows, then stores them pair-wise (float4 table reads + STG.64).
// ============================================================================
__global__ void __launch_bounds__(512, 4)
main_kernel(float* __restrict__ out, int base, int rem)
{
    __shared__ float2   tab[(H_DIM + 1) * TSTR];   // ~34.3 KB
    __shared__ float    th[H_DIM];
    __shared__ uint32_t stage[16][32];             // packed (x & ~0xFF) | rank

    const int tid  = threadIdx.x;
    const int lane = tid & 31;
    const int warp = tid >> 5;    // 0..15
    const int half = lane >> 4;   // 0/1: which row of the pair
    const int le   = lane & 15;   // float2 slot within the 32-wide embed row
    const int c    = blockIdx.x;

    // contiguous run of items for this CTA
    const int cnt   = base + (c < rem ? 1 : 0);
    const int start = c * base + (c < rem ? c : rem);

    int f_cur = -1;

    for (int w = 0; w < cnt; w++) {
        const int item = start + w;
        const int f    = item >> 5;           // 32 items per feature
        const int rg   = item & 31;

        if (f != f_cur) {
            __syncthreads();                  // old table fully consumed
            const float2* gt = &g_table[f][0][0];
            for (int i = tid; i < (H_DIM + 1) * E_DIM; i += 512)
                tab[(i >> 5) * TSTR + (i & 31)] = gt[i];
            if (tid < H_DIM) th[tid] = g_thresh[f][tid];
            __syncthreads();
            f_cur = f;
        }

        const int row0 = rg * ROWS_PER_ITEM + warp * 32;

        // ---- phase A: coalesced load + binary search ----
        const float xv = __ldcs(&g_xT[f][row0 + lane]);
        int r = 0;
        #pragma unroll
        for (int s = 64; s; s >>= 1)
            if (xv > th[r + s - 1]) r += s;
        if (r == 127 && xv > th[127]) r = 128;

        __syncwarp();                         // prev item's stage reads done
        stage[warp][lane] =
            (__float_as_uint(xv) & 0xFFFFFF00u) | (uint32_t)r;
        __syncwarp();                         // publish

        // ---- phase B: 2 rows per step, conflict-free ----
        float* obase = out + (size_t)(row0 + half) * (F_TOT * E_DIM)
                           + f * E_DIM + le * 2;
        const uint32_t* st = &stage[warp][0];

        #pragma unroll
        for (int j = 0; j < 16; j++) {
            const uint32_t pk = st[j * 2 + half];      // broadcast LDS.32
            const int   rj = (int)(pk & 0xFFu);
            const float xj = __uint_as_float(pk & 0xFFFFFF00u);
            const float4 p = *reinterpret_cast<const float4*>(
                &tab[rj * TSTR + le * 2]);             // linear 256 B / half
            float2 o;
            o.x = fmaf(xj, p.x, p.y);
            o.y = fmaf(xj, p.z, p.w);
            __stcs(reinterpret_cast<float2*>(
                       obase + (size_t)(j * 2) * (F_TOT * E_DIM)), o);
        }
    }
}

// ============================================================================
// kernel_launch
// ============================================================================
extern "C" void kernel_launch(void* const* d_in, const int* in_sizes, int n_in,
                              void* d_out, int out_size) {
    const float* x  = (const float*)d_in[0];  // [B, F]
    const float* w1 = (const float*)d_in[1];  // [F, H]
    const float* b1 = (const float*)d_in[2];  // [F, H]
    const float* w2 = (const float*)d_in[3];  // [F, H, E]
    const float* b2 = (const float*)d_in[4];  // [F, E]
    float* out = (float*)d_out;               // [B, F*E]

    int sms = 148;
    cudaDeviceGetAttribute(&sms, cudaDevAttrMultiProcessorCount, 0);
    const int G    = sms * 4;                 // single wave at 4 CTAs/SM
    const int base = N_ITEMS / G;
    const int rem  = N_ITEMS % G;

    prep_kernel<<<512 + F_TOT, 256>>>(x, w1, b1, w2, b2);
    main_kernel<<<G, 512>>>(out, base, rem);
}